// round 7
// baseline (speedup 1.0000x reference)
#include <cuda_runtime.h>
#include <cstdint>
#include <math.h>

// Problem constants
#define BB 64
#define TT 2048
#define II 64
#define HH 128

// ---------- packed f32x2 / fast-math helpers ----------
__device__ __forceinline__ unsigned long long ffma2(unsigned long long a,
                                                    unsigned long long b,
                                                    unsigned long long c) {
    unsigned long long d;
    asm("fma.rn.f32x2 %0, %1, %2, %3;" : "=l"(d) : "l"(a), "l"(b), "l"(c));
    return d;
}
__device__ __forceinline__ unsigned long long fadd2(unsigned long long a,
                                                    unsigned long long b) {
    unsigned long long d;
    asm("add.rn.f32x2 %0, %1, %2;" : "=l"(d) : "l"(a), "l"(b));
    return d;
}
__device__ __forceinline__ float2 unpack2(unsigned long long v) {
    float2 f;
    asm("mov.b64 {%0, %1}, %2;" : "=f"(f.x), "=f"(f.y) : "l"(v));
    return f;
}
__device__ __forceinline__ float tanh_fast(float x) {
    float y;
    asm("tanh.approx.f32 %0, %1;" : "=f"(y) : "f"(x));
    return y;
}

// ============================================================================
// Phase 1: xw[b,t,i] = dot(x[b,t,:], W[i,:]) + b_ih[i] + b_hh[i]
// (unchanged from round 6 — race-free ping-pong pairs)
// ============================================================================
__global__ __launch_bounds__(128) void xw_gemm_kernel(
    const float* __restrict__ x,
    const float* __restrict__ W,
    const float* __restrict__ b_ih,
    const float* __restrict__ b_hh,
    float* __restrict__ out)
{
    const int ROWS = 64;
    const int i = threadIdx.x;
    const long long row0 = (long long)blockIdx.x * ROWS;

    unsigned long long w[32];
    const ulonglong2* Wrow = (const ulonglong2*)(W + i * II);
#pragma unroll
    for (int k = 0; k < 16; k++) {
        ulonglong2 t = Wrow[k];
        w[2 * k]     = t.x;
        w[2 * k + 1] = t.y;
    }
    const float bias = b_ih[i] + b_hh[i];

    __shared__ __align__(16) float xs[4][II];

    const float4* xg = (const float4*)(x + row0 * II);

    float4 pre0 = make_float4(0.f, 0.f, 0.f, 0.f);
    float4 pre1 = pre0;
    if (i < 16) {
        ((float4*)xs[0])[i] = xg[i];
        ((float4*)xs[1])[i] = xg[16 + i];
        pre0 = xg[32 + i];
        pre1 = xg[48 + i];
    }
    __syncthreads();

#pragma unroll 1
    for (int r = 0; r < ROWS; r += 2) {
        const int base = ((r >> 1) & 1) * 2;

        float4 nxt0 = make_float4(0.f, 0.f, 0.f, 0.f);
        float4 nxt1 = nxt0;
        if (i < 16) {
            int ra = (r + 4 < ROWS) ? (r + 4) : 0;
            int rb = (r + 5 < ROWS) ? (r + 5) : 0;
            nxt0 = xg[ra * 16 + i];
            nxt1 = xg[rb * 16 + i];
            ((float4*)xs[base ^ 2])[i]       = pre0;
            ((float4*)xs[(base ^ 2) + 1])[i] = pre1;
        }

#pragma unroll
        for (int s = 0; s < 2; s++) {
            const ulonglong2* hv = (const ulonglong2*)xs[base + s];
            unsigned long long a0 = 0ull, a1 = 0ull, a2 = 0ull, a3 = 0ull;
#pragma unroll
            for (int k = 0; k < 16; k += 2) {
                ulonglong2 hA = hv[k];
                ulonglong2 hB = hv[k + 1];
                a0 = ffma2(w[2 * k],     hA.x, a0);
                a1 = ffma2(w[2 * k + 1], hA.y, a1);
                a2 = ffma2(w[2 * k + 2], hB.x, a2);
                a3 = ffma2(w[2 * k + 3], hB.y, a3);
            }
            unsigned long long sm = fadd2(fadd2(a0, a1), fadd2(a2, a3));
            float2 f = unpack2(sm);
            out[(row0 + r + s) * HH + i] = f.x + f.y + bias;
        }

        __syncthreads();
        pre0 = nxt0;
        pre1 = nxt1;
    }
}

// ============================================================================
// Phase 2: sequential scan. ONE batch per block, 512 threads (16 warps,
// 4/SMSP), j-split x4: output i = tid>>2 computed by 4 lanes (q = tid&3),
// each covering 32 U-columns. Partial sums combined with 3 INDEPENDENT
// shfl_xor(1,2,3) (overlapped latency). tanh computed redundantly by all
// 4 lanes; q==0 stores.
//
// h buffers: quarter q based at float offset q*36 (144B) -> quarter bases on
// banks 0/4/8/12 -> conflict-free broadcast LDS.128.
//
// Time loop unrolled x4 with 4 rotating xw prefetch registers (MLP=4, a full
// body ahead) -- keeps global-load latency off the critical path (R6 win).
// ============================================================================
#define QSTRIDE 36   // floats per quarter slot (32 data + 4 pad)

__global__ __launch_bounds__(512, 1) void rnn_scan_kernel(
    const float* __restrict__ h0,
    const float* __restrict__ U,
    float* __restrict__ out)
{
    const int tid = threadIdx.x;
    const int i   = tid >> 2;      // output index 0..127
    const int q   = tid & 3;       // j-quarter
    const int b   = blockIdx.x;

    __shared__ __align__(16) float h_s[2][4 * QSTRIDE];

    // U row i, this thread's 32 columns -> 16 packed regs
    unsigned long long u[16];
    const ulonglong2* Urow = (const ulonglong2*)(U + i * HH + q * 32);
#pragma unroll
    for (int k = 0; k < 8; k++) {
        ulonglong2 t = Urow[k];
        u[2 * k]     = t.x;
        u[2 * k + 1] = t.y;
    }

    // padded store index for h value j=i: quarter (i>>5), element (i&31)
    const int sidx = (i >> 5) * QSTRIDE + (i & 31);
    if (q == 0) h_s[0][sidx] = h0[b * HH + i];

    float* op = out + (size_t)b * TT * HH + i;

    // prefetch pipeline: xw[s] = input for step t+s (only q==0 lanes)
    float xw[4] = {0.f, 0.f, 0.f, 0.f};
    if (q == 0) {
        xw[0] = op[0];
        xw[1] = op[HH];
        xw[2] = op[2 * HH];
        xw[3] = op[3 * HH];
    }
    __syncthreads();

    float v = 0.f;
#pragma unroll 1
    for (int t = 0; t < TT; t += 4) {
        // issue next 4 prefetches up front (consumed 4+ steps later)
        float nxw[4];
        if (q == 0) {
#pragma unroll
            for (int s = 0; s < 4; s++) {
                int tp = t + 4 + s;
                tp = (tp < TT) ? tp : (TT - 1);
                nxw[s] = op[(size_t)tp * HH];
            }
        }

#pragma unroll
        for (int s = 0; s < 4; s++) {
            // h_{t+s} lives in buffer s&1
            const ulonglong2* hv =
                (const ulonglong2*)(h_s[s & 1] + q * QSTRIDE);
            unsigned long long a0 = 0ull, a1 = 0ull, a2 = 0ull, a3 = 0ull;
#pragma unroll
            for (int k = 0; k < 8; k += 2) {
                ulonglong2 hA = hv[k];
                ulonglong2 hB = hv[k + 1];
                a0 = ffma2(u[2 * k],     hA.x, a0);
                a1 = ffma2(u[2 * k + 1], hA.y, a1);
                a2 = ffma2(u[2 * k + 2], hB.x, a2);
                a3 = ffma2(u[2 * k + 3], hB.y, a3);
            }
            unsigned long long sm = fadd2(fadd2(a0, a1), fadd2(a2, a3));
            float2 f = unpack2(sm);
            float part = f.x + f.y;

            // sum over the 4 lanes of this output: 3 independent shfls
            float p1 = __shfl_xor_sync(0xffffffffu, part, 1);
            float p2 = __shfl_xor_sync(0xffffffffu, part, 2);
            float p3 = __shfl_xor_sync(0xffffffffu, part, 3);
            float tot = (part + p1) + (p2 + p3);

            // all 4 lanes compute tanh (xw garbage on q!=0, never stored)
            float vv = tanh_fast(xw[s] + tot);

            if (q == 0) {
                v = vv;
                op[(size_t)(t + s) * HH] = vv;     // h_t output
                h_s[(s + 1) & 1][sidx]  = vv;      // publish to other buffer
            }
            __syncthreads();
        }

        // rotation: depends on LDGs issued a full body (~4 steps) ago
        if (q == 0) {
            xw[0] = nxw[0];
            xw[1] = nxw[1];
            xw[2] = nxw[2];
            xw[3] = nxw[3];
        }
    }

    if (q == 0) out[(size_t)BB * TT * HH + b * HH + i] = v;
}

// ============================================================================
// Launch
// ============================================================================
extern "C" void kernel_launch(void* const* d_in, const int* in_sizes, int n_in,
                              void* d_out, int out_size)
{
    (void)in_sizes; (void)n_in; (void)out_size;
    const float* x    = (const float*)d_in[0];
    const float* h0   = (const float*)d_in[1];
    const float* W    = (const float*)d_in[2];
    const float* U    = (const float*)d_in[3];
    const float* b_ih = (const float*)d_in[4];
    const float* b_hh = (const float*)d_in[5];
    float* out = (float*)d_out;

    xw_gemm_kernel<<<(BB * TT) / 64, 128>>>(x, W, b_ih, b_hh, out);
    rnn_scan_kernel<<<BB, 512>>>(h0, U, out);
}

// round 8
// speedup vs baseline: 1.4033x; 1.4033x over previous
#include <cuda_runtime.h>
#include <cstdint>
#include <math.h>

// Problem constants
#define BB 64
#define TT 2048
#define II 64
#define HH 128

// ---------- packed f32x2 / fast-math helpers ----------
__device__ __forceinline__ unsigned long long ffma2(unsigned long long a,
                                                    unsigned long long b,
                                                    unsigned long long c) {
    unsigned long long d;
    asm("fma.rn.f32x2 %0, %1, %2, %3;" : "=l"(d) : "l"(a), "l"(b), "l"(c));
    return d;
}
__device__ __forceinline__ unsigned long long fadd2(unsigned long long a,
                                                    unsigned long long b) {
    unsigned long long d;
    asm("add.rn.f32x2 %0, %1, %2;" : "=l"(d) : "l"(a), "l"(b));
    return d;
}
__device__ __forceinline__ float2 unpack2(unsigned long long v) {
    float2 f;
    asm("mov.b64 {%0, %1}, %2;" : "=f"(f.x), "=f"(f.y) : "l"(v));
    return f;
}
__device__ __forceinline__ float tanh_fast(float x) {
    float y;
    asm("tanh.approx.f32 %0, %1;" : "=f"(y) : "f"(x));
    return y;
}

// ============================================================================
// Phase 1: xw[b,t,i] = dot(x[b,t,:], W[i,:]) + b_ih[i] + b_hh[i]
// (unchanged from round 6 — race-free ping-pong pairs)
// ============================================================================
__global__ __launch_bounds__(128) void xw_gemm_kernel(
    const float* __restrict__ x,
    const float* __restrict__ W,
    const float* __restrict__ b_ih,
    const float* __restrict__ b_hh,
    float* __restrict__ out)
{
    const int ROWS = 64;
    const int i = threadIdx.x;
    const long long row0 = (long long)blockIdx.x * ROWS;

    unsigned long long w[32];
    const ulonglong2* Wrow = (const ulonglong2*)(W + i * II);
#pragma unroll
    for (int k = 0; k < 16; k++) {
        ulonglong2 t = Wrow[k];
        w[2 * k]     = t.x;
        w[2 * k + 1] = t.y;
    }
    const float bias = b_ih[i] + b_hh[i];

    __shared__ __align__(16) float xs[4][II];

    const float4* xg = (const float4*)(x + row0 * II);

    float4 pre0 = make_float4(0.f, 0.f, 0.f, 0.f);
    float4 pre1 = pre0;
    if (i < 16) {
        ((float4*)xs[0])[i] = xg[i];
        ((float4*)xs[1])[i] = xg[16 + i];
        pre0 = xg[32 + i];
        pre1 = xg[48 + i];
    }
    __syncthreads();

#pragma unroll 1
    for (int r = 0; r < ROWS; r += 2) {
        const int base = ((r >> 1) & 1) * 2;

        float4 nxt0 = make_float4(0.f, 0.f, 0.f, 0.f);
        float4 nxt1 = nxt0;
        if (i < 16) {
            int ra = (r + 4 < ROWS) ? (r + 4) : 0;
            int rb = (r + 5 < ROWS) ? (r + 5) : 0;
            nxt0 = xg[ra * 16 + i];
            nxt1 = xg[rb * 16 + i];
            ((float4*)xs[base ^ 2])[i]       = pre0;
            ((float4*)xs[(base ^ 2) + 1])[i] = pre1;
        }

#pragma unroll
        for (int s = 0; s < 2; s++) {
            const ulonglong2* hv = (const ulonglong2*)xs[base + s];
            unsigned long long a0 = 0ull, a1 = 0ull, a2 = 0ull, a3 = 0ull;
#pragma unroll
            for (int k = 0; k < 16; k += 2) {
                ulonglong2 hA = hv[k];
                ulonglong2 hB = hv[k + 1];
                a0 = ffma2(w[2 * k],     hA.x, a0);
                a1 = ffma2(w[2 * k + 1], hA.y, a1);
                a2 = ffma2(w[2 * k + 2], hB.x, a2);
                a3 = ffma2(w[2 * k + 3], hB.y, a3);
            }
            unsigned long long sm = fadd2(fadd2(a0, a1), fadd2(a2, a3));
            float2 f = unpack2(sm);
            out[(row0 + r + s) * HH + i] = f.x + f.y + bias;
        }

        __syncthreads();
        pre0 = nxt0;
        pre1 = nxt1;
    }
}

// ============================================================================
// Phase 2: sequential scan. ONE batch per block, 256 threads, j-split x2
// (R6 structure) with four chain/issue cuts:
//  - prefetch LDGs issued at sub-steps 3 and 7 (AFTER the dot), not body top
//  - 8 accumulator chains, depth 4 (shorter FMA chain)
//  - xw pre-added to even lane's partial BEFORE the shfl -> both lanes hold
//    the full pre-activation; both compute tanh; stores split across lanes
//    (even: STS h publish, odd: STG output)
//  - time loop unrolled x8 (MLP=8 on xw, less loop overhead)
// ============================================================================
#define HPAD 68   // hi half starts at float index 68 (byte 272): disjoint banks

__global__ __launch_bounds__(256, 1) void rnn_scan_kernel(
    const float* __restrict__ h0,
    const float* __restrict__ U,
    float* __restrict__ out)
{
    const int tid  = threadIdx.x;
    const int i    = tid >> 1;     // output index 0..127
    const int half = tid & 1;      // j-half
    const int b    = blockIdx.x;

    __shared__ __align__(16) float h_s[2][136];  // [buf][padded h]

    // U row i, this thread's 64 columns -> 32 packed regs
    unsigned long long u[32];
    const ulonglong2* Urow = (const ulonglong2*)(U + i * HH + half * 64);
#pragma unroll
    for (int k = 0; k < 16; k++) {
        ulonglong2 t = Urow[k];
        u[2 * k]     = t.x;
        u[2 * k + 1] = t.y;
    }

    const int sidx = (i < 64) ? i : (i + (HPAD - 64));  // padded store index
    if (half == 0) h_s[0][sidx] = h0[b * HH + i];

    float* op = out + (size_t)b * TT * HH + i;

    // xw pipeline (even lanes only): xw[s] = input for step t+s
    float xw[8];
#pragma unroll
    for (int s = 0; s < 8; s++) xw[s] = 0.f;
    if (half == 0) {
#pragma unroll
        for (int s = 0; s < 8; s++) xw[s] = op[(size_t)s * HH];
    }
    __syncthreads();

    float v = 0.f;
#pragma unroll 1
    for (int t = 0; t < TT; t += 8) {
        float nxw[8];

#pragma unroll
        for (int s = 0; s < 8; s++) {
            // h_{t+s} lives in buffer s&1 (8 even -> parity consistent)
            const ulonglong2* hv = (const ulonglong2*)(h_s[s & 1] + half * HPAD);
            unsigned long long acc0 = 0ull, acc1 = 0ull, acc2 = 0ull, acc3 = 0ull;
            unsigned long long acc4 = 0ull, acc5 = 0ull, acc6 = 0ull, acc7 = 0ull;
#pragma unroll
            for (int k = 0; k < 16; k += 4) {
                ulonglong2 hA = hv[k];
                ulonglong2 hB = hv[k + 1];
                ulonglong2 hC = hv[k + 2];
                ulonglong2 hD = hv[k + 3];
                acc0 = ffma2(u[2 * k],     hA.x, acc0);
                acc1 = ffma2(u[2 * k + 1], hA.y, acc1);
                acc2 = ffma2(u[2 * k + 2], hB.x, acc2);
                acc3 = ffma2(u[2 * k + 3], hB.y, acc3);
                acc4 = ffma2(u[2 * k + 4], hC.x, acc4);
                acc5 = ffma2(u[2 * k + 5], hC.y, acc5);
                acc6 = ffma2(u[2 * k + 6], hD.x, acc6);
                acc7 = ffma2(u[2 * k + 7], hD.y, acc7);
            }
            unsigned long long r0 = fadd2(acc0, acc4);
            unsigned long long r1 = fadd2(acc1, acc5);
            unsigned long long r2 = fadd2(acc2, acc6);
            unsigned long long r3 = fadd2(acc3, acc7);
            unsigned long long rr = fadd2(fadd2(r0, r1), fadd2(r2, r3));
            float2 f = unpack2(rr);
            float part = f.x + f.y;

            // even lane folds xw in BEFORE the exchange
            if (half == 0) part += xw[s];

            // pair exchange: both lanes now hold the full pre-activation
            float tot = part + __shfl_xor_sync(0xffffffffu, part, 1);

            float vv = tanh_fast(tot);
            v = vv;

            if (half == 0) {
                h_s[(s + 1) & 1][sidx] = vv;          // publish new state
            } else {
                op[(size_t)(t + s) * HH] = vv;        // h_t output
            }

            // prefetch behind the dot: 4 LDGs at s==3, 4 at s==7 (even lanes)
            if (s == 3 && half == 0) {
#pragma unroll
                for (int p = 0; p < 4; p++) {
                    int tp = t + 8 + p;
                    tp = (tp < TT) ? tp : (TT - 1);   // tail values never consumed
                    nxw[p] = op[(size_t)tp * HH];
                }
            }
            if (s == 7 && half == 0) {
#pragma unroll
                for (int p = 4; p < 8; p++) {
                    int tp = t + 8 + p;
                    tp = (tp < TT) ? tp : (TT - 1);
                    nxw[p] = op[(size_t)tp * HH];
                }
            }

            __syncthreads();
        }

        if (half == 0) {
#pragma unroll
            for (int s = 0; s < 8; s++) xw[s] = nxw[s];
        }
    }

    // h_last (both lanes hold v; even lane stores)
    if (half == 0) out[(size_t)BB * TT * HH + b * HH + i] = v;
}

// ============================================================================
// Launch
// ============================================================================
extern "C" void kernel_launch(void* const* d_in, const int* in_sizes, int n_in,
                              void* d_out, int out_size)
{
    (void)in_sizes; (void)n_in; (void)out_size;
    const float* x    = (const float*)d_in[0];
    const float* h0   = (const float*)d_in[1];
    const float* W    = (const float*)d_in[2];
    const float* U    = (const float*)d_in[3];
    const float* b_ih = (const float*)d_in[4];
    const float* b_hh = (const float*)d_in[5];
    float* out = (float*)d_out;

    xw_gemm_kernel<<<(BB * TT) / 64, 128>>>(x, W, b_ih, b_hh, out);
    rnn_scan_kernel<<<BB, 256>>>(h0, U, out);
}

// round 9
// speedup vs baseline: 1.5358x; 1.0944x over previous
#include <cuda_runtime.h>
#include <cstdint>
#include <math.h>

// Problem constants
#define BB 64
#define TT 2048
#define II 64
#define HH 128

// ---------- packed f32x2 / fast-math helpers ----------
__device__ __forceinline__ unsigned long long ffma2(unsigned long long a,
                                                    unsigned long long b,
                                                    unsigned long long c) {
    unsigned long long d;
    asm("fma.rn.f32x2 %0, %1, %2, %3;" : "=l"(d) : "l"(a), "l"(b), "l"(c));
    return d;
}
__device__ __forceinline__ unsigned long long fadd2(unsigned long long a,
                                                    unsigned long long b) {
    unsigned long long d;
    asm("add.rn.f32x2 %0, %1, %2;" : "=l"(d) : "l"(a), "l"(b));
    return d;
}
__device__ __forceinline__ float2 unpack2(unsigned long long v) {
    float2 f;
    asm("mov.b64 {%0, %1}, %2;" : "=f"(f.x), "=f"(f.y) : "l"(v));
    return f;
}
__device__ __forceinline__ float tanh_fast(float x) {
    float y;
    asm("tanh.approx.f32 %0, %1;" : "=f"(y) : "f"(x));
    return y;
}

// ============================================================================
// Phase 1: xw[b,t,i] = dot(x[b,t,:], W[i,:]) + b_ih[i] + b_hh[i]
// (unchanged from round 6 — race-free ping-pong pairs)
// ============================================================================
__global__ __launch_bounds__(128) void xw_gemm_kernel(
    const float* __restrict__ x,
    const float* __restrict__ W,
    const float* __restrict__ b_ih,
    const float* __restrict__ b_hh,
    float* __restrict__ out)
{
    const int ROWS = 64;
    const int i = threadIdx.x;
    const long long row0 = (long long)blockIdx.x * ROWS;

    unsigned long long w[32];
    const ulonglong2* Wrow = (const ulonglong2*)(W + i * II);
#pragma unroll
    for (int k = 0; k < 16; k++) {
        ulonglong2 t = Wrow[k];
        w[2 * k]     = t.x;
        w[2 * k + 1] = t.y;
    }
    const float bias = b_ih[i] + b_hh[i];

    __shared__ __align__(16) float xs[4][II];

    const float4* xg = (const float4*)(x + row0 * II);

    float4 pre0 = make_float4(0.f, 0.f, 0.f, 0.f);
    float4 pre1 = pre0;
    if (i < 16) {
        ((float4*)xs[0])[i] = xg[i];
        ((float4*)xs[1])[i] = xg[16 + i];
        pre0 = xg[32 + i];
        pre1 = xg[48 + i];
    }
    __syncthreads();

#pragma unroll 1
    for (int r = 0; r < ROWS; r += 2) {
        const int base = ((r >> 1) & 1) * 2;

        float4 nxt0 = make_float4(0.f, 0.f, 0.f, 0.f);
        float4 nxt1 = nxt0;
        if (i < 16) {
            int ra = (r + 4 < ROWS) ? (r + 4) : 0;
            int rb = (r + 5 < ROWS) ? (r + 5) : 0;
            nxt0 = xg[ra * 16 + i];
            nxt1 = xg[rb * 16 + i];
            ((float4*)xs[base ^ 2])[i]       = pre0;
            ((float4*)xs[(base ^ 2) + 1])[i] = pre1;
        }

#pragma unroll
        for (int s = 0; s < 2; s++) {
            const ulonglong2* hv = (const ulonglong2*)xs[base + s];
            unsigned long long a0 = 0ull, a1 = 0ull, a2 = 0ull, a3 = 0ull;
#pragma unroll
            for (int k = 0; k < 16; k += 2) {
                ulonglong2 hA = hv[k];
                ulonglong2 hB = hv[k + 1];
                a0 = ffma2(w[2 * k],     hA.x, a0);
                a1 = ffma2(w[2 * k + 1], hA.y, a1);
                a2 = ffma2(w[2 * k + 2], hB.x, a2);
                a3 = ffma2(w[2 * k + 3], hB.y, a3);
            }
            unsigned long long sm = fadd2(fadd2(a0, a1), fadd2(a2, a3));
            float2 f = unpack2(sm);
            out[(row0 + r + s) * HH + i] = f.x + f.y + bias;
        }

        __syncthreads();
        pre0 = nxt0;
        pre1 = nxt1;
    }
}

// ============================================================================
// Phase 2: sequential scan. ONE batch per block, 128 threads (1 warp/SMSP),
// FULL dot per thread (no shfl — j-split removed: it never reduced per-SMSP
// FFMA issue, only added a 26-cyc shfl and cross-warp contention).
//  - thread i owns output i: 32 broadcast LDS.128 + 64 FFMA2 (8 acc chains,
//    depth 8 -> reduced tree), MUFU tanh, STS publish + STG output
//  - xw reg-ring depth 8; LDGs issued behind the dot at s==3 / s==7
//  - one bar.sync(4 warps) per step; h double-buffered
// ============================================================================
__global__ __launch_bounds__(128, 1) void rnn_scan_kernel(
    const float* __restrict__ h0,
    const float* __restrict__ U,
    float* __restrict__ out)
{
    const int i = threadIdx.x;     // output index 0..127
    const int b = blockIdx.x;

    __shared__ __align__(16) float h_s[2][HH];

    // U row i (128 floats) -> 64 packed regs
    unsigned long long u[64];
    const ulonglong2* Urow = (const ulonglong2*)(U + i * HH);
#pragma unroll
    for (int k = 0; k < 32; k++) {
        ulonglong2 t = Urow[k];
        u[2 * k]     = t.x;
        u[2 * k + 1] = t.y;
    }

    h_s[0][i] = h0[b * HH + i];

    float* op = out + (size_t)b * TT * HH + i;

    // xw pipeline: xw[s] = input for step t+s
    float xw[8];
#pragma unroll
    for (int s = 0; s < 8; s++) xw[s] = op[(size_t)s * HH];
    __syncthreads();

    float v = 0.f;
#pragma unroll 1
    for (int t = 0; t < TT; t += 8) {
        float nxw[8];

#pragma unroll
        for (int s = 0; s < 8; s++) {
            // h_{t+s} lives in buffer s&1 (8 even -> parity consistent)
            const ulonglong2* hv = (const ulonglong2*)h_s[s & 1];
            unsigned long long acc0 = 0ull, acc1 = 0ull, acc2 = 0ull, acc3 = 0ull;
            unsigned long long acc4 = 0ull, acc5 = 0ull, acc6 = 0ull, acc7 = 0ull;
#pragma unroll
            for (int k = 0; k < 32; k += 4) {
                ulonglong2 hA = hv[k];
                ulonglong2 hB = hv[k + 1];
                ulonglong2 hC = hv[k + 2];
                ulonglong2 hD = hv[k + 3];
                acc0 = ffma2(u[2 * k],     hA.x, acc0);
                acc1 = ffma2(u[2 * k + 1], hA.y, acc1);
                acc2 = ffma2(u[2 * k + 2], hB.x, acc2);
                acc3 = ffma2(u[2 * k + 3], hB.y, acc3);
                acc4 = ffma2(u[2 * k + 4], hC.x, acc4);
                acc5 = ffma2(u[2 * k + 5], hC.y, acc5);
                acc6 = ffma2(u[2 * k + 6], hD.x, acc6);
                acc7 = ffma2(u[2 * k + 7], hD.y, acc7);
            }
            unsigned long long r0 = fadd2(acc0, acc4);
            unsigned long long r1 = fadd2(acc1, acc5);
            unsigned long long r2 = fadd2(acc2, acc6);
            unsigned long long r3 = fadd2(acc3, acc7);
            unsigned long long rr = fadd2(fadd2(r0, r1), fadd2(r2, r3));
            float2 f = unpack2(rr);

            float vv = tanh_fast((xw[s] + f.x) + f.y);
            v = vv;

            h_s[(s + 1) & 1][i]      = vv;   // publish new state (other buffer)
            op[(size_t)(t + s) * HH] = vv;   // h_t output (overwrites xw[t])

            // prefetch behind the dot: 4 LDGs at s==3, 4 at s==7
            if (s == 3) {
#pragma unroll
                for (int p = 0; p < 4; p++) {
                    int tp = t + 8 + p;
                    tp = (tp < TT) ? tp : (TT - 1);   // tail values never consumed
                    nxw[p] = op[(size_t)tp * HH];
                }
            }
            if (s == 7) {
#pragma unroll
                for (int p = 4; p < 8; p++) {
                    int tp = t + 8 + p;
                    tp = (tp < TT) ? tp : (TT - 1);
                    nxw[p] = op[(size_t)tp * HH];
                }
            }

            __syncthreads();
        }

#pragma unroll
        for (int s = 0; s < 8; s++) xw[s] = nxw[s];
    }

    out[(size_t)BB * TT * HH + b * HH + i] = v;   // h_last
}

// ============================================================================
// Launch
// ============================================================================
extern "C" void kernel_launch(void* const* d_in, const int* in_sizes, int n_in,
                              void* d_out, int out_size)
{
    (void)in_sizes; (void)n_in; (void)out_size;
    const float* x    = (const float*)d_in[0];
    const float* h0   = (const float*)d_in[1];
    const float* W    = (const float*)d_in[2];
    const float* U    = (const float*)d_in[3];
    const float* b_ih = (const float*)d_in[4];
    const float* b_hh = (const float*)d_in[5];
    float* out = (float*)d_out;

    xw_gemm_kernel<<<(BB * TT) / 64, 128>>>(x, W, b_ih, b_hh, out);
    rnn_scan_kernel<<<BB, 128>>>(h0, U, out);
}

// round 10
// speedup vs baseline: 1.7614x; 1.1469x over previous
#include <cuda_runtime.h>
#include <cstdint>
#include <math.h>

// Problem constants
#define BB 64
#define TT 2048
#define II 64
#define HH 128
#define CH 8             // steps per chunk
#define NCH (TT / CH)    // 256 chunks

// ---------- packed f32x2 / fast-math helpers ----------
__device__ __forceinline__ unsigned long long ffma2(unsigned long long a,
                                                    unsigned long long b,
                                                    unsigned long long c) {
    unsigned long long d;
    asm("fma.rn.f32x2 %0, %1, %2, %3;" : "=l"(d) : "l"(a), "l"(b), "l"(c));
    return d;
}
__device__ __forceinline__ unsigned long long fadd2(unsigned long long a,
                                                    unsigned long long b) {
    unsigned long long d;
    asm("add.rn.f32x2 %0, %1, %2;" : "=l"(d) : "l"(a), "l"(b));
    return d;
}
__device__ __forceinline__ float2 unpack2(unsigned long long v) {
    float2 f;
    asm("mov.b64 {%0, %1}, %2;" : "=f"(f.x), "=f"(f.y) : "l"(v));
    return f;
}
__device__ __forceinline__ float tanh_fast(float x) {
    float y;
    asm("tanh.approx.f32 %0, %1;" : "=f"(y) : "f"(x));
    return y;
}

// ============================================================================
// Fused RNN kernel: one block per batch element, 256 threads.
//   warps 0-3  (tid   0-127): PRODUCER — stages x (LDG->smem, 2 chunks ahead),
//              computes xw chunk k+1 (input GEMM), copies o_ring chunk k-1 to
//              global output.
//   warps 4-7  (tid 128-255): CONSUMER — the sequential recurrence. Thread
//              i = tid-128 owns output i. Per step: broadcast LDS of h_{t-1}
//              from o_ring, 64 FFMA2 against U row (regs), MUFU tanh, STS to
//              o_ring. NO global ops in the step. Consumer warps have the
//              higher wids -> arbiter priority over producer.
// Rings (smem): o_ring[16] = h history + output staging (2 chunk halves),
//               xw_r[16] = xw staging (2 halves), x_r[2] = staged x chunks.
// Sync: __syncthreads at chunk boundaries (uniform control flow);
//       bar.sync 1,128 consumer-only between steps within a chunk.
// ============================================================================
__global__ __launch_bounds__(256, 1) void rnn_fused_kernel(
    const float* __restrict__ x,
    const float* __restrict__ h0,
    const float* __restrict__ W,
    const float* __restrict__ U,
    const float* __restrict__ b_ih,
    const float* __restrict__ b_hh,
    float* __restrict__ out)
{
    const int tid = threadIdx.x;
    const int b   = blockIdx.x;
    const bool is_consumer = (tid >= 128);
    const int lid = tid & 127;          // role-local id (i for consumer, p for producer)

    __shared__ __align__(16) float o_ring[16][HH];    // 8 KB
    __shared__ __align__(16) float xw_r[16][HH];      // 8 KB
    __shared__ __align__(16) float x_r[2][CH][II];    // 2 KB

    const float* xb = x   + (size_t)b * TT * II;
    float*       ob = out + (size_t)b * TT * HH;

    // ---- role-specific register state ----
    unsigned long long u[64];   // consumer: U row (128 floats packed)
    unsigned long long w[32];   // producer: W row (64 floats packed)
    float bias = 0.f;

    if (is_consumer) {
        const ulonglong2* Urow = (const ulonglong2*)(U + lid * HH);
#pragma unroll
        for (int k = 0; k < 32; k++) {
            ulonglong2 t = Urow[k];
            u[2 * k]     = t.x;
            u[2 * k + 1] = t.y;
        }
        o_ring[15][lid] = h0[b * HH + lid];   // h_{-1} lives in slot 15
    } else {
        const ulonglong2* Wrow = (const ulonglong2*)(W + lid * II);
#pragma unroll
        for (int k = 0; k < 16; k++) {
            ulonglong2 t = Wrow[k];
            w[2 * k]     = t.x;
            w[2 * k + 1] = t.y;
        }
        bias = b_ih[lid] + b_hh[lid];
        // stage x chunks 0 and 1
        const float4* xg = (const float4*)xb;      // 16 float4 per timestep
        int row = lid >> 4, c4 = lid & 15;
        ((float4*)x_r[0][row])[c4] = xg[(0 * CH + row) * 16 + c4];
        ((float4*)x_r[1][row])[c4] = xg[(1 * CH + row) * 16 + c4];
    }

    __syncthreads();   // x chunks 0,1 staged; h0 published

    if (!is_consumer) {
        // compute xw chunk 0 into xw_r[0..7]
#pragma unroll 1
        for (int s = 0; s < CH; s++) {
            const ulonglong2* xv = (const ulonglong2*)x_r[0][s];
            unsigned long long a0 = 0ull, a1 = 0ull, a2 = 0ull, a3 = 0ull;
#pragma unroll
            for (int k = 0; k < 16; k += 2) {
                ulonglong2 hA = xv[k];
                ulonglong2 hB = xv[k + 1];
                a0 = ffma2(w[2 * k],     hA.x, a0);
                a1 = ffma2(w[2 * k + 1], hA.y, a1);
                a2 = ffma2(w[2 * k + 2], hB.x, a2);
                a3 = ffma2(w[2 * k + 3], hB.y, a3);
            }
            unsigned long long sm = fadd2(fadd2(a0, a1), fadd2(a2, a3));
            float2 f = unpack2(sm);
            xw_r[s][lid] = f.x + f.y + bias;
        }
    }

    float v = 0.f;

#pragma unroll 1
    for (int k = 0; k < NCH; k++) {
        __syncthreads();   // boundary: xw chunk k ready; o_ring chunk k-1 final
        const int half = k & 1;

        if (is_consumer) {
            // preload this chunk's xw values (ready long before use)
            float xwv[CH];
#pragma unroll
            for (int s = 0; s < CH; s++) xwv[s] = xw_r[half * CH + s][lid];

#pragma unroll
            for (int s = 0; s < CH; s++) {
                const float* hprev = (s == 0)
                    ? o_ring[((k + 1) & 1) * CH + (CH - 1)]   // last slot of other half
                    : o_ring[half * CH + s - 1];
                const ulonglong2* hv = (const ulonglong2*)hprev;

                unsigned long long acc0 = 0ull, acc1 = 0ull, acc2 = 0ull, acc3 = 0ull;
                unsigned long long acc4 = 0ull, acc5 = 0ull, acc6 = 0ull, acc7 = 0ull;
#pragma unroll
                for (int kk = 0; kk < 32; kk += 4) {
                    ulonglong2 hA = hv[kk];
                    ulonglong2 hB = hv[kk + 1];
                    ulonglong2 hC = hv[kk + 2];
                    ulonglong2 hD = hv[kk + 3];
                    acc0 = ffma2(u[2 * kk],     hA.x, acc0);
                    acc1 = ffma2(u[2 * kk + 1], hA.y, acc1);
                    acc2 = ffma2(u[2 * kk + 2], hB.x, acc2);
                    acc3 = ffma2(u[2 * kk + 3], hB.y, acc3);
                    acc4 = ffma2(u[2 * kk + 4], hC.x, acc4);
                    acc5 = ffma2(u[2 * kk + 5], hC.y, acc5);
                    acc6 = ffma2(u[2 * kk + 6], hD.x, acc6);
                    acc7 = ffma2(u[2 * kk + 7], hD.y, acc7);
                }
                unsigned long long r0 = fadd2(acc0, acc4);
                unsigned long long r1 = fadd2(acc1, acc5);
                unsigned long long r2 = fadd2(acc2, acc6);
                unsigned long long r3 = fadd2(acc3, acc7);
                unsigned long long rr = fadd2(fadd2(r0, r1), fadd2(r2, r3));
                float2 f = unpack2(rr);

                float vv = tanh_fast((xwv[s] + f.x) + f.y);
                v = vv;
                o_ring[half * CH + s][lid] = vv;   // publish (STS only)

                if (s < CH - 1)
                    asm volatile("bar.sync 1, 128;" ::: "memory");
                // s == CH-1: next read happens after the loop-top __syncthreads
            }
        } else {
            // ---- producer ----
            // (a) copy o_ring chunk k-1 to global output
            if (k > 0) {
                const int c    = k - 1;
                const int chalf = c & 1;
                const int wid  = lid >> 5;       // 0..3
                const int lane = lid & 31;
#pragma unroll
                for (int jj = 0; jj < 2; jj++) {
                    int j = 2 * wid + jj;                       // slot in chunk
                    float4 val = ((const float4*)o_ring[chalf * CH + j])[lane];
                    ((float4*)(ob + (size_t)(c * CH + j) * HH))[lane] = val;
                }
            }
            // (b) stage x chunk k+2 (consumed while computing xw chunk k+2
            //     during iteration k+1)
            if (k + 2 < NCH) {
                const float4* xg = (const float4*)xb;
                int row = lid >> 4, c4 = lid & 15;
                ((float4*)x_r[k & 1][row])[c4] =
                    xg[((k + 2) * CH + row) * 16 + c4];
            }
            // (c) compute xw chunk k+1 from x chunk k+1 (staged at iter k-1)
            if (k + 1 < NCH) {
                const int nhalf = (k + 1) & 1;
#pragma unroll 1
                for (int s = 0; s < CH; s++) {
                    const ulonglong2* xv = (const ulonglong2*)x_r[nhalf][s];
                    unsigned long long a0 = 0ull, a1 = 0ull, a2 = 0ull, a3 = 0ull;
#pragma unroll
                    for (int kk = 0; kk < 16; kk += 2) {
                        ulonglong2 hA = xv[kk];
                        ulonglong2 hB = xv[kk + 1];
                        a0 = ffma2(w[2 * kk],     hA.x, a0);
                        a1 = ffma2(w[2 * kk + 1], hA.y, a1);
                        a2 = ffma2(w[2 * kk + 2], hB.x, a2);
                        a3 = ffma2(w[2 * kk + 3], hB.y, a3);
                    }
                    unsigned long long sm = fadd2(fadd2(a0, a1), fadd2(a2, a3));
                    float2 f = unpack2(sm);
                    xw_r[nhalf * CH + s][lid] = f.x + f.y + bias;
                }
            }
        }
    }

    __syncthreads();   // last chunk's o_ring final

    if (!is_consumer) {
        // copy final chunk (NCH-1) to global
        const int c     = NCH - 1;
        const int chalf = c & 1;
        const int wid   = lid >> 5;
        const int lane  = lid & 31;
#pragma unroll
        for (int jj = 0; jj < 2; jj++) {
            int j = 2 * wid + jj;
            float4 val = ((const float4*)o_ring[chalf * CH + j])[lane];
            ((float4*)(ob + (size_t)(c * CH + j) * HH))[lane] = val;
        }
    } else {
        out[(size_t)BB * TT * HH + b * HH + lid] = v;   // h_last
    }
}

// ============================================================================
// Launch
// ============================================================================
extern "C" void kernel_launch(void* const* d_in, const int* in_sizes, int n_in,
                              void* d_out, int out_size)
{
    (void)in_sizes; (void)n_in; (void)out_size;
    const float* x    = (const float*)d_in[0];
    const float* h0   = (const float*)d_in[1];
    const float* W    = (const float*)d_in[2];
    const float* U    = (const float*)d_in[3];
    const float* b_ih = (const float*)d_in[4];
    const float* b_hh = (const float*)d_in[5];
    float* out = (float*)d_out;

    rnn_fused_kernel<<<BB, 256>>>(x, h0, W, U, b_ih, b_hh, out);
}

// round 11
// speedup vs baseline: 1.8230x; 1.0350x over previous
#include <cuda_runtime.h>
#include <cstdint>
#include <math.h>

// Problem constants
#define BB 64
#define TT 2048
#define II 64
#define HH 128
#define CH 16            // steps per chunk
#define NCH (TT / CH)    // 128 chunks

// ---------- packed f32x2 / fast-math helpers ----------
__device__ __forceinline__ unsigned long long ffma2(unsigned long long a,
                                                    unsigned long long b,
                                                    unsigned long long c) {
    unsigned long long d;
    asm("fma.rn.f32x2 %0, %1, %2, %3;" : "=l"(d) : "l"(a), "l"(b), "l"(c));
    return d;
}
__device__ __forceinline__ unsigned long long fadd2(unsigned long long a,
                                                    unsigned long long b) {
    unsigned long long d;
    asm("add.rn.f32x2 %0, %1, %2;" : "=l"(d) : "l"(a), "l"(b));
    return d;
}
__device__ __forceinline__ float2 unpack2(unsigned long long v) {
    float2 f;
    asm("mov.b64 {%0, %1}, %2;" : "=f"(f.x), "=f"(f.y) : "l"(v));
    return f;
}
__device__ __forceinline__ unsigned long long pack2(float lo, float hi) {
    unsigned long long v;
    asm("mov.b64 %0, {%1, %2};" : "=l"(v) : "f"(lo), "f"(hi));
    return v;
}
__device__ __forceinline__ float tanh_fast(float x) {
    float y;
    asm("tanh.approx.f32 %0, %1;" : "=f"(y) : "f"(x));
    return y;
}

// ============================================================================
// Fused RNN kernel: one block per batch element, 256 threads.
//   warps 0-3  (tid   0-127): PRODUCER — stages x (LDG->smem, 2 chunks ahead),
//              computes xw chunk k+1, copies o_ring chunk k-1 to global.
//   warps 4-7  (tid 128-255): CONSUMER — the sequential recurrence. Thread
//              i = tid-128 owns output i. Per step: broadcast LDS of h_{t-1},
//              64 FFMA2 (xw folded into acc0 init), MUFU tanh, STS publish.
//              NO global ops in the step.
// ============================================================================
__global__ __launch_bounds__(256, 1) void rnn_fused_kernel(
    const float* __restrict__ x,
    const float* __restrict__ h0,
    const float* __restrict__ W,
    const float* __restrict__ U,
    const float* __restrict__ b_ih,
    const float* __restrict__ b_hh,
    float* __restrict__ out)
{
    const int tid = threadIdx.x;
    const int b   = blockIdx.x;
    const bool is_consumer = (tid >= 128);
    const int lid = tid & 127;

    __shared__ __align__(16) float o_ring[2 * CH][HH];   // 16 KB
    __shared__ __align__(16) float xw_r[2 * CH][HH];     // 16 KB
    __shared__ __align__(16) float x_r[2][CH][II];       // 8 KB

    const float* xb = x   + (size_t)b * TT * II;
    float*       ob = out + (size_t)b * TT * HH;

    unsigned long long u[64];   // consumer: U row
    unsigned long long w[32];   // producer: W row
    float bias = 0.f;

    if (is_consumer) {
        const ulonglong2* Urow = (const ulonglong2*)(U + lid * HH);
#pragma unroll
        for (int k = 0; k < 32; k++) {
            ulonglong2 t = Urow[k];
            u[2 * k]     = t.x;
            u[2 * k + 1] = t.y;
        }
        o_ring[2 * CH - 1][lid] = h0[b * HH + lid];   // h_{-1} in last slot
    } else {
        const ulonglong2* Wrow = (const ulonglong2*)(W + lid * II);
#pragma unroll
        for (int k = 0; k < 16; k++) {
            ulonglong2 t = Wrow[k];
            w[2 * k]     = t.x;
            w[2 * k + 1] = t.y;
        }
        bias = b_ih[lid] + b_hh[lid];
        // stage x chunks 0 and 1 (each: CH rows x 16 float4 = 256 float4)
        const float4* xg = (const float4*)xb;
        int c4 = lid & 15;
#pragma unroll
        for (int rr = 0; rr < 2; rr++) {
            int row = (lid >> 4) + rr * 8;
            ((float4*)x_r[0][row])[c4] = xg[(0 * CH + row) * 16 + c4];
            ((float4*)x_r[1][row])[c4] = xg[(1 * CH + row) * 16 + c4];
        }
    }

    __syncthreads();

    if (!is_consumer) {
        // xw chunk 0 into xw_r[0..CH)
#pragma unroll 1
        for (int s = 0; s < CH; s++) {
            const ulonglong2* xv = (const ulonglong2*)x_r[0][s];
            unsigned long long a0 = 0ull, a1 = 0ull, a2 = 0ull, a3 = 0ull;
#pragma unroll
            for (int k = 0; k < 16; k += 2) {
                ulonglong2 hA = xv[k];
                ulonglong2 hB = xv[k + 1];
                a0 = ffma2(w[2 * k],     hA.x, a0);
                a1 = ffma2(w[2 * k + 1], hA.y, a1);
                a2 = ffma2(w[2 * k + 2], hB.x, a2);
                a3 = ffma2(w[2 * k + 3], hB.y, a3);
            }
            unsigned long long sm = fadd2(fadd2(a0, a1), fadd2(a2, a3));
            float2 f = unpack2(sm);
            xw_r[s][lid] = f.x + f.y + bias;
        }
    }

    float v = 0.f;

#pragma unroll 1
    for (int k = 0; k < NCH; k++) {
        __syncthreads();   // xw chunk k ready; o_ring chunk k-1 final
        const int half = k & 1;

        if (is_consumer) {
            // preload this chunk's xw values
            float xwv[CH];
#pragma unroll
            for (int s = 0; s < CH; s++) xwv[s] = xw_r[half * CH + s][lid];

#pragma unroll
            for (int s = 0; s < CH; s++) {
                const float* hprev = (s == 0)
                    ? o_ring[((k + 1) & 1) * CH + (CH - 1)]
                    : o_ring[half * CH + s - 1];
                const ulonglong2* hv = (const ulonglong2*)hprev;

                // acc0 seeded with (xw, 0): folds the xw add into the chain
                unsigned long long acc0 = pack2(xwv[s], 0.f);
                unsigned long long acc1 = 0ull, acc2 = 0ull, acc3 = 0ull;
                unsigned long long acc4 = 0ull, acc5 = 0ull, acc6 = 0ull, acc7 = 0ull;
#pragma unroll
                for (int kk = 0; kk < 32; kk += 4) {
                    ulonglong2 hA = hv[kk];
                    ulonglong2 hB = hv[kk + 1];
                    ulonglong2 hC = hv[kk + 2];
                    ulonglong2 hD = hv[kk + 3];
                    acc0 = ffma2(u[2 * kk],     hA.x, acc0);
                    acc1 = ffma2(u[2 * kk + 1], hA.y, acc1);
                    acc2 = ffma2(u[2 * kk + 2], hB.x, acc2);
                    acc3 = ffma2(u[2 * kk + 3], hB.y, acc3);
                    acc4 = ffma2(u[2 * kk + 4], hC.x, acc4);
                    acc5 = ffma2(u[2 * kk + 5], hC.y, acc5);
                    acc6 = ffma2(u[2 * kk + 6], hD.x, acc6);
                    acc7 = ffma2(u[2 * kk + 7], hD.y, acc7);
                }
                unsigned long long r0 = fadd2(acc0, acc4);
                unsigned long long r1 = fadd2(acc1, acc5);
                unsigned long long r2 = fadd2(acc2, acc6);
                unsigned long long r3 = fadd2(acc3, acc7);
                unsigned long long rr = fadd2(fadd2(r0, r1), fadd2(r2, r3));
                float2 f = unpack2(rr);

                float vv = tanh_fast(f.x + f.y);
                v = vv;
                o_ring[half * CH + s][lid] = vv;   // publish (STS only)

                if (s < CH - 1)
                    asm volatile("bar.sync 1, 128;" ::: "memory");
            }
        } else {
            // ---- producer ----
            // (b) FIRST: stage x chunk k+2 (longest latency, consumed iter k+1)
            if (k + 2 < NCH) {
                const float4* xg = (const float4*)xb;
                int c4 = lid & 15;
#pragma unroll
                for (int rr = 0; rr < 2; rr++) {
                    int row = (lid >> 4) + rr * 8;
                    ((float4*)x_r[k & 1][row])[c4] =
                        xg[((k + 2) * CH + row) * 16 + c4];
                }
            }
            // (c) xw chunk k+1 from x chunk k+1
            if (k + 1 < NCH) {
                const int nhalf = (k + 1) & 1;
#pragma unroll 1
                for (int s = 0; s < CH; s++) {
                    const ulonglong2* xv = (const ulonglong2*)x_r[nhalf][s];
                    unsigned long long a0 = 0ull, a1 = 0ull, a2 = 0ull, a3 = 0ull;
#pragma unroll
                    for (int kk = 0; kk < 16; kk += 2) {
                        ulonglong2 hA = xv[kk];
                        ulonglong2 hB = xv[kk + 1];
                        a0 = ffma2(w[2 * kk],     hA.x, a0);
                        a1 = ffma2(w[2 * kk + 1], hA.y, a1);
                        a2 = ffma2(w[2 * kk + 2], hB.x, a2);
                        a3 = ffma2(w[2 * kk + 3], hB.y, a3);
                    }
                    unsigned long long sm = fadd2(fadd2(a0, a1), fadd2(a2, a3));
                    float2 f = unpack2(sm);
                    xw_r[nhalf * CH + s][lid] = f.x + f.y + bias;
                }
            }
            // (a) LAST: copy o_ring chunk k-1 to global output
            if (k > 0) {
                const int c     = k - 1;
                const int chalf = c & 1;
                const int wid   = lid >> 5;       // 0..3
                const int lane  = lid & 31;
#pragma unroll
                for (int jj = 0; jj < 4; jj++) {
                    int j = 4 * wid + jj;                        // slot 0..15
                    float4 val = ((const float4*)o_ring[chalf * CH + j])[lane];
                    ((float4*)(ob + (size_t)(c * CH + j) * HH))[lane] = val;
                }
            }
        }
    }

    __syncthreads();   // last chunk's o_ring final

    if (!is_consumer) {
        const int c     = NCH - 1;
        const int chalf = c & 1;
        const int wid   = lid >> 5;
        const int lane  = lid & 31;
#pragma unroll
        for (int jj = 0; jj < 4; jj++) {
            int j = 4 * wid + jj;
            float4 val = ((const float4*)o_ring[chalf * CH + j])[lane];
            ((float4*)(ob + (size_t)(c * CH + j) * HH))[lane] = val;
        }
    } else {
        out[(size_t)BB * TT * HH + b * HH + lid] = v;   // h_last
    }
}

// ============================================================================
// Launch
// ============================================================================
extern "C" void kernel_launch(void* const* d_in, const int* in_sizes, int n_in,
                              void* d_out, int out_size)
{
    (void)in_sizes; (void)n_in; (void)out_size;
    const float* x    = (const float*)d_in[0];
    const float* h0   = (const float*)d_in[1];
    const float* W    = (const float*)d_in[2];
    const float* U    = (const float*)d_in[3];
    const float* b_ih = (const float*)d_in[4];
    const float* b_hh = (const float*)d_in[5];
    float* out = (float*)d_out;

    rnn_fused_kernel<<<BB, 256>>>(x, h0, W, U, b_ih, b_hh, out);
}

// round 12
// speedup vs baseline: 1.8481x; 1.0138x over previous
#include <cuda_runtime.h>
#include <cstdint>
#include <math.h>

// Problem constants
#define BB 64
#define TT 2048
#define II 64
#define HH 128
#define CH 16            // steps per chunk
#define NCH (TT / CH)    // 128 chunks

// ---------- packed f32x2 / fast-math helpers ----------
__device__ __forceinline__ unsigned long long ffma2(unsigned long long a,
                                                    unsigned long long b,
                                                    unsigned long long c) {
    unsigned long long d;
    asm("fma.rn.f32x2 %0, %1, %2, %3;" : "=l"(d) : "l"(a), "l"(b), "l"(c));
    return d;
}
__device__ __forceinline__ unsigned long long fadd2(unsigned long long a,
                                                    unsigned long long b) {
    unsigned long long d;
    asm("add.rn.f32x2 %0, %1, %2;" : "=l"(d) : "l"(a), "l"(b));
    return d;
}
__device__ __forceinline__ float2 unpack2(unsigned long long v) {
    float2 f;
    asm("mov.b64 {%0, %1}, %2;" : "=f"(f.x), "=f"(f.y) : "l"(v));
    return f;
}
__device__ __forceinline__ unsigned long long pack2(float lo, float hi) {
    unsigned long long v;
    asm("mov.b64 %0, {%1, %2};" : "=l"(v) : "f"(lo), "f"(hi));
    return v;
}
__device__ __forceinline__ float tanh_fast(float x) {
    float y;
    asm("tanh.approx.f32 %0, %1;" : "=f"(y) : "f"(x));
    return y;
}

// ============================================================================
// Fused RNN kernel: one block per batch element, 256 threads.
//   warps 0-3: PRODUCER (x staging, xw GEMM one chunk ahead, output copy)
//   warps 4-7: CONSUMER — the recurrence. REGISTER-LEAN version: no xwv
//     preload array (xw read via one LDS per step, folded into acc0 seed),
//     4 accumulator chains. Target: fit u[64] (128 regs) + working set
//     without spills.
// ============================================================================
__global__ __launch_bounds__(256, 1) void rnn_fused_kernel(
    const float* __restrict__ x,
    const float* __restrict__ h0,
    const float* __restrict__ W,
    const float* __restrict__ U,
    const float* __restrict__ b_ih,
    const float* __restrict__ b_hh,
    float* __restrict__ out)
{
    const int tid = threadIdx.x;
    const int b   = blockIdx.x;
    const bool is_consumer = (tid >= 128);
    const int lid = tid & 127;

    __shared__ __align__(16) float o_ring[2 * CH][HH];   // 16 KB
    __shared__ __align__(16) float xw_r[2 * CH][HH];     // 16 KB
    __shared__ __align__(16) float x_r[2][CH][II];       // 8 KB

    const float* xb = x   + (size_t)b * TT * II;
    float*       ob = out + (size_t)b * TT * HH;

    unsigned long long u[64];   // consumer: U row (128 floats packed)
    unsigned long long w[32];   // producer: W row
    float bias = 0.f;

    if (is_consumer) {
        const ulonglong2* Urow = (const ulonglong2*)(U + lid * HH);
#pragma unroll
        for (int k = 0; k < 32; k++) {
            ulonglong2 t = Urow[k];
            u[2 * k]     = t.x;
            u[2 * k + 1] = t.y;
        }
        o_ring[2 * CH - 1][lid] = h0[b * HH + lid];   // h_{-1} in last slot
    } else {
        const ulonglong2* Wrow = (const ulonglong2*)(W + lid * II);
#pragma unroll
        for (int k = 0; k < 16; k++) {
            ulonglong2 t = Wrow[k];
            w[2 * k]     = t.x;
            w[2 * k + 1] = t.y;
        }
        bias = b_ih[lid] + b_hh[lid];
        const float4* xg = (const float4*)xb;
        int c4 = lid & 15;
#pragma unroll
        for (int rr = 0; rr < 2; rr++) {
            int row = (lid >> 4) + rr * 8;
            ((float4*)x_r[0][row])[c4] = xg[(0 * CH + row) * 16 + c4];
            ((float4*)x_r[1][row])[c4] = xg[(1 * CH + row) * 16 + c4];
        }
    }

    __syncthreads();

    if (!is_consumer) {
        // xw chunk 0
#pragma unroll 1
        for (int s = 0; s < CH; s++) {
            const ulonglong2* xv = (const ulonglong2*)x_r[0][s];
            unsigned long long a0 = 0ull, a1 = 0ull, a2 = 0ull, a3 = 0ull;
#pragma unroll
            for (int k = 0; k < 16; k += 2) {
                ulonglong2 hA = xv[k];
                ulonglong2 hB = xv[k + 1];
                a0 = ffma2(w[2 * k],     hA.x, a0);
                a1 = ffma2(w[2 * k + 1], hA.y, a1);
                a2 = ffma2(w[2 * k + 2], hB.x, a2);
                a3 = ffma2(w[2 * k + 3], hB.y, a3);
            }
            unsigned long long sm = fadd2(fadd2(a0, a1), fadd2(a2, a3));
            float2 f = unpack2(sm);
            xw_r[s][lid] = f.x + f.y + bias;
        }
    }

    float v = 0.f;

#pragma unroll 1
    for (int k = 0; k < NCH; k++) {
        __syncthreads();   // xw chunk k ready; o_ring chunk k-1 final
        const int half = k & 1;

        if (is_consumer) {
#pragma unroll
            for (int s = 0; s < CH; s++) {
                const float* hprev = (s == 0)
                    ? o_ring[((k + 1) & 1) * CH + (CH - 1)]
                    : o_ring[half * CH + s - 1];
                const ulonglong2* hv = (const ulonglong2*)hprev;

                // xw via single LDS, folded into acc0 seed (no reg array)
                unsigned long long acc0 = pack2(xw_r[half * CH + s][lid], 0.f);
                unsigned long long acc1 = 0ull, acc2 = 0ull, acc3 = 0ull;
#pragma unroll
                for (int kk = 0; kk < 32; kk += 2) {
                    ulonglong2 hA = hv[kk];
                    ulonglong2 hB = hv[kk + 1];
                    acc0 = ffma2(u[2 * kk],     hA.x, acc0);
                    acc1 = ffma2(u[2 * kk + 1], hA.y, acc1);
                    acc2 = ffma2(u[2 * kk + 2], hB.x, acc2);
                    acc3 = ffma2(u[2 * kk + 3], hB.y, acc3);
                }
                unsigned long long rr = fadd2(fadd2(acc0, acc1),
                                              fadd2(acc2, acc3));
                float2 f = unpack2(rr);

                float vv = tanh_fast(f.x + f.y);
                v = vv;
                o_ring[half * CH + s][lid] = vv;   // publish (STS only)

                if (s < CH - 1)
                    asm volatile("bar.sync 1, 128;" ::: "memory");
            }
        } else {
            // ---- producer ----
            // stage x chunk k+2 first (longest latency)
            if (k + 2 < NCH) {
                const float4* xg = (const float4*)xb;
                int c4 = lid & 15;
#pragma unroll
                for (int rr = 0; rr < 2; rr++) {
                    int row = (lid >> 4) + rr * 8;
                    ((float4*)x_r[k & 1][row])[c4] =
                        xg[((k + 2) * CH + row) * 16 + c4];
                }
            }
            // xw chunk k+1
            if (k + 1 < NCH) {
                const int nhalf = (k + 1) & 1;
#pragma unroll 1
                for (int s = 0; s < CH; s++) {
                    const ulonglong2* xv = (const ulonglong2*)x_r[nhalf][s];
                    unsigned long long a0 = 0ull, a1 = 0ull, a2 = 0ull, a3 = 0ull;
#pragma unroll
                    for (int kk = 0; kk < 16; kk += 2) {
                        ulonglong2 hA = xv[kk];
                        ulonglong2 hB = xv[kk + 1];
                        a0 = ffma2(w[2 * kk],     hA.x, a0);
                        a1 = ffma2(w[2 * kk + 1], hA.y, a1);
                        a2 = ffma2(w[2 * kk + 2], hB.x, a2);
                        a3 = ffma2(w[2 * kk + 3], hB.y, a3);
                    }
                    unsigned long long sm = fadd2(fadd2(a0, a1), fadd2(a2, a3));
                    float2 f = unpack2(sm);
                    xw_r[nhalf * CH + s][lid] = f.x + f.y + bias;
                }
            }
            // copy o_ring chunk k-1 to global
            if (k > 0) {
                const int c     = k - 1;
                const int chalf = c & 1;
                const int wid   = lid >> 5;
                const int lane  = lid & 31;
#pragma unroll
                for (int jj = 0; jj < 4; jj++) {
                    int j = 4 * wid + jj;
                    float4 val = ((const float4*)o_ring[chalf * CH + j])[lane];
                    ((float4*)(ob + (size_t)(c * CH + j) * HH))[lane] = val;
                }
            }
        }
    }

    __syncthreads();

    if (!is_consumer) {
        const int c     = NCH - 1;
        const int chalf = c & 1;
        const int wid   = lid >> 5;
        const int lane  = lid & 31;
#pragma unroll
        for (int jj = 0; jj < 4; jj++) {
            int j = 4 * wid + jj;
            float4 val = ((const float4*)o_ring[chalf * CH + j])[lane];
            ((float4*)(ob + (size_t)(c * CH + j) * HH))[lane] = val;
        }
    } else {
        out[(size_t)BB * TT * HH + b * HH + lid] = v;   // h_last
    }
}

// ============================================================================
// Launch
// ============================================================================
extern "C" void kernel_launch(void* const* d_in, const int* in_sizes, int n_in,
                              void* d_out, int out_size)
{
    (void)in_sizes; (void)n_in; (void)out_size;
    const float* x    = (const float*)d_in[0];
    const float* h0   = (const float*)d_in[1];
    const float* W    = (const float*)d_in[2];
    const float* U    = (const float*)d_in[3];
    const float* b_ih = (const float*)d_in[4];
    const float* b_hh = (const float*)d_in[5];
    float* out = (float*)d_out;

    rnn_fused_kernel<<<BB, 256>>>(x, h0, W, U, b_ih, b_hh, out);
}

// round 14
// speedup vs baseline: 2.0058x; 1.0853x over previous
#include <cuda_runtime.h>
#include <cstdint>

// Problem constants
#define BB 64
#define TT 2048
#define II 64
#define HH 128
#define CH 16            // timesteps per flag chunk
#define NCH (TT / CH)    // 128 chunks

// Producer->consumer chunk flags. Zero-initialized at module load; each
// consumer resets its batch's flags to 0 after use -> every launch (and every
// graph replay) starts from all-zero. Producer sets 1 with release semantics.
__device__ int g_flags[BB][NCH];

// ---------- packed f32x2 / fast-math helpers ----------
__device__ __forceinline__ unsigned long long ffma2(unsigned long long a,
                                                    unsigned long long b,
                                                    unsigned long long c) {
    unsigned long long d;
    asm("fma.rn.f32x2 %0, %1, %2, %3;" : "=l"(d) : "l"(a), "l"(b), "l"(c));
    return d;
}
__device__ __forceinline__ unsigned long long fadd2(unsigned long long a,
                                                    unsigned long long b) {
    unsigned long long d;
    asm("add.rn.f32x2 %0, %1, %2;" : "=l"(d) : "l"(a), "l"(b));
    return d;
}
__device__ __forceinline__ float2 unpack2(unsigned long long v) {
    float2 f;
    asm("mov.b64 {%0, %1}, %2;" : "=f"(f.x), "=f"(f.y) : "l"(v));
    return f;
}
__device__ __forceinline__ unsigned long long pack2(float lo, float hi) {
    unsigned long long v;
    asm("mov.b64 %0, {%1, %2};" : "=l"(v) : "f"(lo), "f"(hi));
    return v;
}
__device__ __forceinline__ float tanh_fast(float x) {
    float y;
    asm("tanh.approx.f32 %0, %1;" : "=f"(y) : "f"(x));
    return y;
}
__device__ __forceinline__ int ld_acquire(const int* p) {
    int v;
    asm volatile("ld.global.acquire.gpu.b32 %0, [%1];" : "=r"(v) : "l"(p) : "memory");
    return v;
}
__device__ __forceinline__ void st_release(int* p, int v) {
    asm volatile("st.global.release.gpu.b32 [%0], %1;" :: "l"(p), "r"(v) : "memory");
}

// ============================================================================
// One kernel, grid = 128 x 256 threads.
//   blocks [0, 64):   PRODUCER for batch b = blockIdx.x. Computes
//     xw[b,t,i] = W x_t + b_ih + b_hh into out[b,t,:] (in-place region the
//     consumer later overwrites with h_t), one CH-chunk at a time, releasing
//     g_flags[b][k] per chunk. 256 threads: thread (half=tid>>7, i=tid&127)
//     computes rows half*8..half*8+7 of each chunk for output dim i.
//   blocks [64, 128):  CONSUMER for batch b = blockIdx.x - 64. Threads >= 128
//     exit; threads 0..127 run the recurrence (named barriers only):
//     per step: 16 broadcast LDS.128 (h) + 64 FFMA2 + MUFU tanh + STS + STG.
//     xw read from out via an 8-deep register ring (prefetch behind the dot);
//     chunk readiness verified via flag loads issued one body early.
// ============================================================================
__global__ __launch_bounds__(256, 1) void rnn_split_kernel(
    const float* __restrict__ x,
    const float* __restrict__ h0,
    const float* __restrict__ W,
    const float* __restrict__ U,
    const float* __restrict__ b_ih,
    const float* __restrict__ b_hh,
    float* __restrict__ out)
{
    __shared__ __align__(16) float sh[2 * CH * II];   // 8 KB, role-punned
    const int tid = threadIdx.x;

    if (blockIdx.x < BB) {
        // ==================== PRODUCER ====================
        const int b    = blockIdx.x;
        const int i    = tid & 127;
        const int half = tid >> 7;
        float (*xs)[CH][II] = (float (*)[CH][II])sh;

        unsigned long long w[32];
        const ulonglong2* Wrow = (const ulonglong2*)(W + i * II);
#pragma unroll
        for (int k = 0; k < 16; k++) {
            ulonglong2 t = Wrow[k];
            w[2 * k]     = t.x;
            w[2 * k + 1] = t.y;
        }
        const float bias = b_ih[i] + b_hh[i];

        const float4* xg = (const float4*)(x + (size_t)b * TT * II);
        float* ob = out + (size_t)b * TT * HH;

        const int srow = tid >> 4;   // 0..15
        const int sc4  = tid & 15;   // float4 within row

        // stage chunk 0
        ((float4*)xs[0][srow])[sc4] = xg[(size_t)srow * 16 + sc4];
        __syncthreads();

#pragma unroll 1
        for (int k = 0; k < NCH; k++) {
            const int buf = k & 1;
            // stage chunk k+1 into the other buffer (read next iteration)
            if (k + 1 < NCH)
                ((float4*)xs[buf ^ 1][srow])[sc4] =
                    xg[((size_t)(k + 1) * CH + srow) * 16 + sc4];

            // compute this thread's 8 rows of chunk k
#pragma unroll 1
            for (int s = 0; s < 8; s++) {
                const int row = half * 8 + s;
                const ulonglong2* xv = (const ulonglong2*)xs[buf][row];
                unsigned long long a0 = 0ull, a1 = 0ull, a2 = 0ull, a3 = 0ull;
#pragma unroll
                for (int kk = 0; kk < 16; kk += 2) {
                    ulonglong2 hA = xv[kk];
                    ulonglong2 hB = xv[kk + 1];
                    a0 = ffma2(w[2 * kk],     hA.x, a0);
                    a1 = ffma2(w[2 * kk + 1], hA.y, a1);
                    a2 = ffma2(w[2 * kk + 2], hB.x, a2);
                    a3 = ffma2(w[2 * kk + 3], hB.y, a3);
                }
                unsigned long long sm = fadd2(fadd2(a0, a1), fadd2(a2, a3));
                float2 f = unpack2(sm);
                ob[(size_t)(k * CH + row) * HH + i] = f.x + f.y + bias;
            }

            __threadfence();     // each thread orders its own xw stores
            __syncthreads();     // all fences done (and xs[buf] fully read)
            if (tid == 0) st_release(&g_flags[b][k], 1);
        }
        return;
    }

    // ==================== CONSUMER ====================
    if (tid >= 128) return;      // threads 128..255 exit (named bars only below)
    const int b = blockIdx.x - BB;
    const int i = tid;

    float (*h_s)[HH] = (float (*)[HH])sh;   // h double buffer (first 1 KB)

    // U row i (128 floats) -> 64 packed regs
    unsigned long long u[64];
    const ulonglong2* Urow = (const ulonglong2*)(U + i * HH);
#pragma unroll
    for (int k = 0; k < 32; k++) {
        ulonglong2 t = Urow[k];
        u[2 * k]     = t.x;
        u[2 * k + 1] = t.y;
    }

    h_s[0][i] = h0[b * HH + i];

    float* op = out + (size_t)b * TT * HH + i;

    // wait for chunk 0 (covers xw[0..15])
    while (ld_acquire(&g_flags[b][0]) != 1) __nanosleep(64);

    // flag pipeline: `pending` holds the (early-issued) load of flag[cleared+1]
    int cleared = 0;
    int pending = (NCH > 1) ? ld_acquire(&g_flags[b][1]) : 1;

    // xw ring: xw[s] = input for step t+s
    float xw[8];
#pragma unroll
    for (int s = 0; s < 8; s++) xw[s] = op[(size_t)s * HH];

    asm volatile("bar.sync 1, 128;" ::: "memory");   // h0 visible

    float v = 0.f;
#pragma unroll 1
    for (int t = 0; t < TT; t += 8) {
        // this body's loads reach xw[t+15] -> need chunks up to (t+15)>>4
        int hi = (t + 15) >> 4;
        if (hi > NCH - 1) hi = NCH - 1;
        if (hi > cleared) {
            while (pending != 1) {
                __nanosleep(64);
                pending = ld_acquire(&g_flags[b][cleared + 1]);
            }
            cleared++;
            pending = (cleared + 1 < NCH) ? ld_acquire(&g_flags[b][cleared + 1]) : 1;
        }

        float nxw[8];
#pragma unroll
        for (int s = 0; s < 8; s++) {
            const ulonglong2* hv = (const ulonglong2*)h_s[s & 1];

            // lo lane accumulates xw + dot-lo; hi lane accumulates dot-hi
            unsigned long long acc0 = pack2(xw[s], 0.f);
            unsigned long long acc1 = 0ull, acc2 = 0ull, acc3 = 0ull;
#pragma unroll
            for (int kk = 0; kk < 32; kk += 2) {
                ulonglong2 hA = hv[kk];
                ulonglong2 hB = hv[kk + 1];
                acc0 = ffma2(u[2 * kk],     hA.x, acc0);
                acc1 = ffma2(u[2 * kk + 1], hA.y, acc1);
                acc2 = ffma2(u[2 * kk + 2], hB.x, acc2);
                acc3 = ffma2(u[2 * kk + 3], hB.y, acc3);
            }
            unsigned long long rr = fadd2(fadd2(acc0, acc1), fadd2(acc2, acc3));
            float2 f = unpack2(rr);

            float vv = tanh_fast(f.x + f.y);
            v = vv;

            h_s[(s + 1) & 1][i]      = vv;   // publish new state
            op[(size_t)(t + s) * HH] = vv;   // h_t output (overwrites xw[t])

            // prefetch behind the dot: 4 LDGs at s==3, 4 at s==7
            if (s == 3) {
#pragma unroll
                for (int p = 0; p < 4; p++) {
                    int tp = t + 8 + p;
                    tp = (tp < TT) ? tp : (TT - 1);   // tail values never consumed
                    nxw[p] = op[(size_t)tp * HH];
                }
            }
            if (s == 7) {
#pragma unroll
                for (int p = 4; p < 8; p++) {
                    int tp = t + 8 + p;
                    tp = (tp < TT) ? tp : (TT - 1);
                    nxw[p] = op[(size_t)tp * HH];
                }
            }

            asm volatile("bar.sync 1, 128;" ::: "memory");
        }

#pragma unroll
        for (int s = 0; s < 8; s++) xw[s] = nxw[s];
    }

    out[(size_t)BB * TT * HH + b * HH + i] = v;   // h_last

    // reset this batch's flags for the next launch/replay (128 == NCH)
    g_flags[b][i] = 0;
}

// ============================================================================
// Launch
// ============================================================================
extern "C" void kernel_launch(void* const* d_in, const int* in_sizes, int n_in,
                              void* d_out, int out_size)
{
    (void)in_sizes; (void)n_in; (void)out_size;
    const float* x    = (const float*)d_in[0];
    const float* h0   = (const float*)d_in[1];
    const float* W    = (const float*)d_in[2];
    const float* U    = (const float*)d_in[3];
    const float* b_ih = (const float*)d_in[4];
    const float* b_hh = (const float*)d_in[5];
    float* out = (float*)d_out;

    rnn_split_kernel<<<2 * BB, 256>>>(x, h0, W, U, b_ih, b_hh, out);
}

// round 15
// speedup vs baseline: 2.1242x; 1.0590x over previous
#include <cuda_runtime.h>
#include <cstdint>

// Problem constants
#define BB 64
#define TT 2048
#define II 64
#define HH 128
#define CH 16            // timesteps per flag chunk == consumer body
#define NCH (TT / CH)    // 128 chunks

// Producer->consumer chunk flags. Zero-initialized at module load; consumers
// reset their batch's flags after use -> replay-safe.
__device__ int g_flags[BB][NCH];

// ---------- packed f32x2 / fast-math helpers ----------
__device__ __forceinline__ unsigned long long ffma2(unsigned long long a,
                                                    unsigned long long b,
                                                    unsigned long long c) {
    unsigned long long d;
    asm("fma.rn.f32x2 %0, %1, %2, %3;" : "=l"(d) : "l"(a), "l"(b), "l"(c));
    return d;
}
__device__ __forceinline__ unsigned long long fadd2(unsigned long long a,
                                                    unsigned long long b) {
    unsigned long long d;
    asm("add.rn.f32x2 %0, %1, %2;" : "=l"(d) : "l"(a), "l"(b));
    return d;
}
__device__ __forceinline__ float2 unpack2(unsigned long long v) {
    float2 f;
    asm("mov.b64 {%0, %1}, %2;" : "=f"(f.x), "=f"(f.y) : "l"(v));
    return f;
}
__device__ __forceinline__ unsigned long long pack2(float lo, float hi) {
    unsigned long long v;
    asm("mov.b64 %0, {%1, %2};" : "=l"(v) : "f"(lo), "f"(hi));
    return v;
}
__device__ __forceinline__ float tanh_fast(float x) {
    float y;
    asm("tanh.approx.f32 %0, %1;" : "=f"(y) : "f"(x));
    return y;
}
__device__ __forceinline__ int ld_acquire(const int* p) {
    int v;
    asm volatile("ld.global.acquire.gpu.b32 %0, [%1];" : "=r"(v) : "l"(p) : "memory");
    return v;
}
__device__ __forceinline__ void st_release(int* p, int v) {
    asm volatile("st.global.release.gpu.b32 [%0], %1;" :: "l"(p), "r"(v) : "memory");
}

// ============================================================================
// grid = 128 x 256.  blocks [0,64): producer (xw GEMM into out in-place,
// per-chunk release flags).  blocks [64,128): consumer (threads 0..127 run
// the recurrence; 16-deep h ring; one bar.sync 1,128 per step).
// ============================================================================
__global__ __launch_bounds__(256, 1) void rnn_split_kernel(
    const float* __restrict__ x,
    const float* __restrict__ h0,
    const float* __restrict__ W,
    const float* __restrict__ U,
    const float* __restrict__ b_ih,
    const float* __restrict__ b_hh,
    float* __restrict__ out)
{
    __shared__ __align__(16) float sh[CH * HH];   // 8 KB, role-punned
    const int tid = threadIdx.x;

    if (blockIdx.x < BB) {
        // ==================== PRODUCER ====================
        const int b    = blockIdx.x;
        const int i    = tid & 127;
        const int half = tid >> 7;
        float (*xs)[CH / 2][II] = (float (*)[CH / 2][II])sh;   // 2 bufs x 8 rows? no:
        // layout: sh as xs2[2][16][64] won't fit 8KB? 2*16*64*4 = 8192 B. fits.
        float (*xs2)[CH][II] = (float (*)[CH][II])sh;

        unsigned long long w[32];
        const ulonglong2* Wrow = (const ulonglong2*)(W + i * II);
#pragma unroll
        for (int k = 0; k < 16; k++) {
            ulonglong2 t = Wrow[k];
            w[2 * k]     = t.x;
            w[2 * k + 1] = t.y;
        }
        const float bias = b_ih[i] + b_hh[i];

        const float4* xg = (const float4*)(x + (size_t)b * TT * II);
        float* ob = out + (size_t)b * TT * HH;

        const int srow = tid >> 4;   // 0..15
        const int sc4  = tid & 15;

        ((float4*)xs2[0][srow])[sc4] = xg[(size_t)srow * 16 + sc4];
        __syncthreads();

#pragma unroll 1
        for (int k = 0; k < NCH; k++) {
            const int buf = k & 1;
            if (k + 1 < NCH)
                ((float4*)xs2[buf ^ 1][srow])[sc4] =
                    xg[((size_t)(k + 1) * CH + srow) * 16 + sc4];

#pragma unroll 1
            for (int s = 0; s < 8; s++) {
                const int row = half * 8 + s;
                const ulonglong2* xv = (const ulonglong2*)xs2[buf][row];
                unsigned long long a0 = 0ull, a1 = 0ull, a2 = 0ull, a3 = 0ull;
#pragma unroll
                for (int kk = 0; kk < 16; kk += 2) {
                    ulonglong2 hA = xv[kk];
                    ulonglong2 hB = xv[kk + 1];
                    a0 = ffma2(w[2 * kk],     hA.x, a0);
                    a1 = ffma2(w[2 * kk + 1], hA.y, a1);
                    a2 = ffma2(w[2 * kk + 2], hB.x, a2);
                    a3 = ffma2(w[2 * kk + 3], hB.y, a3);
                }
                unsigned long long sm = fadd2(fadd2(a0, a1), fadd2(a2, a3));
                float2 f = unpack2(sm);
                ob[(size_t)(k * CH + row) * HH + i] = f.x + f.y + bias;
            }

            __threadfence();
            __syncthreads();
            if (tid == 0) st_release(&g_flags[b][k], 1);
        }
        return;
    }

    // ==================== CONSUMER ====================
    if (tid >= 128) return;
    const int b = blockIdx.x - BB;
    const int i = tid;

    float (*ring)[HH] = (float (*)[HH])sh;   // 16-deep h ring

    unsigned long long u[64];
    const ulonglong2* Urow = (const ulonglong2*)(U + i * HH);
#pragma unroll
    for (int k = 0; k < 32; k++) {
        ulonglong2 t = Urow[k];
        u[2 * k]     = t.x;
        u[2 * k + 1] = t.y;
    }

    ring[CH - 1][i] = h0[b * HH + i];        // h_{-1} in slot 15

    float* op = out + (size_t)b * TT * HH + i;

    while (ld_acquire(&g_flags[b][0]) != 1) __nanosleep(64);

    // pipelined flag for chunk 1 (checked at the END of body 0, one body late)
    int pending = (NCH > 1) ? ld_acquire(&g_flags[b][1]) : 1;

    // xw ring for this body's 16 steps
    float xw[CH];
#pragma unroll
    for (int s = 0; s < CH; s++) xw[s] = op[(size_t)s * HH];

    asm volatile("bar.sync 1, 128;" ::: "memory");

    float v = 0.f;
#pragma unroll 1
    for (int t = 0; t < TT; t += CH) {
        const int kchunk = t >> 4;
        const bool more = (t + CH < TT);
        float nxw[CH];

        // flag gate for the prefetches issued later this body (chunk k+1).
        // `pending` was loaded one full body ago -> steady state: no spin.
        if (more) {
            while (pending != 1) {
                __nanosleep(64);
                pending = ld_acquire(&g_flags[b][kchunk + 1]);
            }
            pending = (kchunk + 2 < NCH) ? ld_acquire(&g_flags[b][kchunk + 2]) : 1;
        }

#pragma unroll
        for (int s = 0; s < CH; s++) {
            const ulonglong2* hv = (const ulonglong2*)ring[(s + CH - 1) & (CH - 1)];

            // 2 accumulator chains (spacing 6 cyc > lat 4); xw seeded in lo
            unsigned long long acc0 = pack2(xw[s], 0.f);
            unsigned long long acc1 = 0ull;
#pragma unroll
            for (int kk = 0; kk < 32; kk++) {
                ulonglong2 hA = hv[kk];
                acc0 = ffma2(u[2 * kk],     hA.x, acc0);
                acc1 = ffma2(u[2 * kk + 1], hA.y, acc1);
            }
            unsigned long long rr = fadd2(acc0, acc1);
            float2 f = unpack2(rr);

            float vv = tanh_fast(f.x + f.y);
            v = vv;

            ring[s][i]               = vv;   // publish h_t (slot = s)
            op[(size_t)(t + s) * HH] = vv;   // output (coalesced STG.32)

            // prefetch next body's xw: 4 LDGs at each of s=12..15
            if (more && s >= 12) {
#pragma unroll
                for (int p = 0; p < 4; p++) {
                    int tp = t + CH + (s - 12) * 4 + p;
                    nxw[(s - 12) * 4 + p] = op[(size_t)tp * HH];
                }
            }

            asm volatile("bar.sync 1, 128;" ::: "memory");
        }

        if (more) {
#pragma unroll
            for (int s = 0; s < CH; s++) xw[s] = nxw[s];
        }
    }

    out[(size_t)BB * TT * HH + b * HH + i] = v;   // h_last

    g_flags[b][i] = 0;   // reset for next launch/replay (NCH == 128)
}

// ============================================================================
// Launch
// ============================================================================
extern "C" void kernel_launch(void* const* d_in, const int* in_sizes, int n_in,
                              void* d_out, int out_size)
{
    (void)in_sizes; (void)n_in; (void)out_size;
    const float* x    = (const float*)d_in[0];
    const float* h0   = (const float*)d_in[1];
    const float* W    = (const float*)d_in[2];
    const float* U    = (const float*)d_in[3];
    const float* b_ih = (const float*)d_in[4];
    const float* b_hh = (const float*)d_in[5];
    float* out = (float*)d_out;

    rnn_split_kernel<<<2 * BB, 256>>>(x, h0, W, U, b_ih, b_hh, out);
}

// round 16
// speedup vs baseline: 2.3514x; 1.1070x over previous
#include <cuda_runtime.h>
#include <cstdint>

// Problem constants
#define BB 64
#define TT 2048
#define II 64
#define HH 128
#define CH 16            // timesteps per chunk
#define NCH (TT / CH)    // 128 chunks

// Producer->consumer chunk flags. Zero-initialized at module load; consumers
// reset their batch's flags after use -> replay-safe.
__device__ int g_flags[BB][NCH];

// ---------- packed f32x2 / fast-math helpers ----------
__device__ __forceinline__ unsigned long long ffma2(unsigned long long a,
                                                    unsigned long long b,
                                                    unsigned long long c) {
    unsigned long long d;
    asm("fma.rn.f32x2 %0, %1, %2, %3;" : "=l"(d) : "l"(a), "l"(b), "l"(c));
    return d;
}
__device__ __forceinline__ unsigned long long fadd2(unsigned long long a,
                                                    unsigned long long b) {
    unsigned long long d;
    asm("add.rn.f32x2 %0, %1, %2;" : "=l"(d) : "l"(a), "l"(b));
    return d;
}
__device__ __forceinline__ float2 unpack2(unsigned long long v) {
    float2 f;
    asm("mov.b64 {%0, %1}, %2;" : "=f"(f.x), "=f"(f.y) : "l"(v));
    return f;
}
__device__ __forceinline__ unsigned long long pack2(float lo, float hi) {
    unsigned long long v;
    asm("mov.b64 %0, {%1, %2};" : "=l"(v) : "f"(lo), "f"(hi));
    return v;
}
__device__ __forceinline__ float tanh_fast(float x) {
    float y;
    asm("tanh.approx.f32 %0, %1;" : "=f"(y) : "f"(x));
    return y;
}
__device__ __forceinline__ int ld_acquire(const int* p) {
    int v;
    asm volatile("ld.global.acquire.gpu.b32 %0, [%1];" : "=r"(v) : "l"(p) : "memory");
    return v;
}
__device__ __forceinline__ void st_release(int* p, int v) {
    asm volatile("st.global.release.gpu.b32 [%0], %1;" :: "l"(p), "r"(v) : "memory");
}

// ============================================================================
// grid = 128 x 256.
//  blocks [0,64):  PRODUCER for batch b (identical to R15): xw = Wx+bias into
//    out in-place, per-chunk release flags.
//  blocks [64,128): CONSUMER for batch b-64, warp-specialized:
//    warps 0-3 (tid   0..127)  = HELPERS: flag waits, LDG xw chunk -> smem,
//                                LDS h chunk -> STG out. All global traffic.
//    warps 4-7 (tid 128..255)  = RECURRENCE: per chunk 16 hoisted xw LDS;
//      per step 32 LDS.128 (h bcast) + 64 FFMA2 + tanh + STS + bar.sync(1,128).
//      NO global memory ops, no flags, no rotation.
//    One __syncthreads per chunk swaps the double-buffered halves.
// ============================================================================
__global__ __launch_bounds__(256, 1) void rnn_split_kernel(
    const float* __restrict__ x,
    const float* __restrict__ h0,
    const float* __restrict__ W,
    const float* __restrict__ U,
    const float* __restrict__ b_ih,
    const float* __restrict__ b_hh,
    float* __restrict__ out)
{
    // consumer blocks: ring = h slots [2*CH][HH] (16KB), xw_s (16KB)
    // producer blocks: first 8KB reused as x staging
    __shared__ __align__(16) float ring[2 * CH][HH];
    __shared__ __align__(16) float xw_s[2 * CH][HH];
    const int tid = threadIdx.x;

    if (blockIdx.x < BB) {
        // ==================== PRODUCER (unchanged from R15) ====================
        const int b    = blockIdx.x;
        const int i    = tid & 127;
        const int half = tid >> 7;
        float (*xs2)[CH][II] = (float (*)[CH][II])ring;   // 8KB of ring reused

        unsigned long long w[32];
        const ulonglong2* Wrow = (const ulonglong2*)(W + i * II);
#pragma unroll
        for (int k = 0; k < 16; k++) {
            ulonglong2 t = Wrow[k];
            w[2 * k]     = t.x;
            w[2 * k + 1] = t.y;
        }
        const float bias = b_ih[i] + b_hh[i];

        const float4* xg = (const float4*)(x + (size_t)b * TT * II);
        float* ob = out + (size_t)b * TT * HH;

        const int srow = tid >> 4;
        const int sc4  = tid & 15;

        ((float4*)xs2[0][srow])[sc4] = xg[(size_t)srow * 16 + sc4];
        __syncthreads();

#pragma unroll 1
        for (int k = 0; k < NCH; k++) {
            const int buf = k & 1;
            if (k + 1 < NCH)
                ((float4*)xs2[buf ^ 1][srow])[sc4] =
                    xg[((size_t)(k + 1) * CH + srow) * 16 + sc4];

#pragma unroll 1
            for (int s = 0; s < 8; s++) {
                const int row = half * 8 + s;
                const ulonglong2* xv = (const ulonglong2*)xs2[buf][row];
                unsigned long long a0 = 0ull, a1 = 0ull, a2 = 0ull, a3 = 0ull;
#pragma unroll
                for (int kk = 0; kk < 16; kk += 2) {
                    ulonglong2 hA = xv[kk];
                    ulonglong2 hB = xv[kk + 1];
                    a0 = ffma2(w[2 * kk],     hA.x, a0);
                    a1 = ffma2(w[2 * kk + 1], hA.y, a1);
                    a2 = ffma2(w[2 * kk + 2], hB.x, a2);
                    a3 = ffma2(w[2 * kk + 3], hB.y, a3);
                }
                unsigned long long sm = fadd2(fadd2(a0, a1), fadd2(a2, a3));
                float2 f = unpack2(sm);
                ob[(size_t)(k * CH + row) * HH + i] = f.x + f.y + bias;
            }

            __threadfence();
            __syncthreads();
            if (tid == 0) st_release(&g_flags[b][k], 1);
        }
        return;
    }

    // ==================== CONSUMER BLOCK ====================
    const int b = blockIdx.x - BB;
    const bool is_rec = (tid >= 128);     // warps 4-7: recurrence
    const int i = tid & 127;              // rec: output idx; helper: lane id
    float* ob = out + (size_t)b * TT * HH;

    unsigned long long u[64];
    if (is_rec) {
        const ulonglong2* Urow = (const ulonglong2*)(U + i * HH);
#pragma unroll
        for (int k = 0; k < 32; k++) {
            ulonglong2 t = Urow[k];
            u[2 * k]     = t.x;
            u[2 * k + 1] = t.y;
        }
        ring[2 * CH - 1][i] = h0[b * HH + i];   // h_{-1} in slot 31
    } else {
        // helpers: wait for chunk 0 and stage it into xw buf 0
        while (ld_acquire(&g_flags[b][0]) != 1) __nanosleep(64);
        const float4* src = (const float4*)ob;          // chunk 0 = out[0..16)
        float4*       dst = (float4*)&xw_s[0][0];       // 512 float4
#pragma unroll
        for (int j = 0; j < 4; j++) dst[i + 128 * j] = src[i + 128 * j];
    }

    float v = 0.f;

#pragma unroll 1
    for (int k = 0; k < NCH; k++) {
        __syncthreads();   // xw chunk k staged; h chunk k-1 final; bufs swap
        const int half = k & 1;

        if (is_rec) {
            // hoist this chunk's 16 xw values (LDS, conflict-free rows)
            float xwv[CH];
#pragma unroll
            for (int s = 0; s < CH; s++) xwv[s] = xw_s[half * CH + s][i];

#pragma unroll
            for (int s = 0; s < CH; s++) {
                const ulonglong2* hv = (const ulonglong2*)(
                    (s == 0) ? ring[(half ^ 1) * CH + (CH - 1)]
                             : ring[half * CH + s - 1]);

                unsigned long long acc0 = pack2(xwv[s], 0.f);
                unsigned long long acc1 = 0ull;
#pragma unroll
                for (int kk = 0; kk < 32; kk++) {
                    ulonglong2 hA = hv[kk];
                    acc0 = ffma2(u[2 * kk],     hA.x, acc0);
                    acc1 = ffma2(u[2 * kk + 1], hA.y, acc1);
                }
                float2 f = unpack2(fadd2(acc0, acc1));

                float vv = tanh_fast(f.x + f.y);
                v = vv;
                ring[half * CH + s][i] = vv;      // publish h_t (STS only)

                if (s < CH - 1)
                    asm volatile("bar.sync 1, 128;" ::: "memory");
                // s == CH-1: covered by next loop-top __syncthreads
            }
        } else {
            // ---- helpers: all global traffic, big slack ----
            // stage xw chunk k+1 into buf half^1 (rec reads it next chunk)
            if (k + 1 < NCH) {
                while (ld_acquire(&g_flags[b][k + 1]) != 1) __nanosleep(64);
                const float4* src = (const float4*)(ob + (size_t)(k + 1) * CH * HH);
                float4*       dst = (float4*)&xw_s[(half ^ 1) * CH][0];
#pragma unroll
                for (int j = 0; j < 4; j++) dst[i + 128 * j] = src[i + 128 * j];
            }
            // drain h chunk k-1 (slots (half^1)*CH ..) to global output
            if (k > 0) {
                const float4* src = (const float4*)&ring[(half ^ 1) * CH][0];
                float4*       dst = (float4*)(ob + (size_t)(k - 1) * CH * HH);
#pragma unroll
                for (int j = 0; j < 4; j++) dst[i + 128 * j] = src[i + 128 * j];
            }
        }
    }

    __syncthreads();   // last chunk's h final in ring

    if (is_rec) {
        out[(size_t)BB * TT * HH + b * HH + i] = v;   // h_last
    } else {
        // drain final chunk (NCH-1), slots ((NCH-1)&1)*CH ..
        const int half = (NCH - 1) & 1;
        const float4* src = (const float4*)&ring[half * CH][0];
        float4*       dst = (float4*)(ob + (size_t)(NCH - 1) * CH * HH);
#pragma unroll
        for (int j = 0; j < 4; j++) dst[i + 128 * j] = src[i + 128 * j];
        // reset this batch's flags for the next launch/replay (NCH == 128)
        g_flags[b][i] = 0;
    }
}

// ============================================================================
// Launch
// ============================================================================
extern "C" void kernel_launch(void* const* d_in, const int* in_sizes, int n_in,
                              void* d_out, int out_size)
{
    (void)in_sizes; (void)n_in; (void)out_size;
    const float* x    = (const float*)d_in[0];
    const float* h0   = (const float*)d_in[1];
    const float* W    = (const float*)d_in[2];
    const float* U    = (const float*)d_in[3];
    const float* b_ih = (const float*)d_in[4];
    const float* b_hh = (const float*)d_in[5];
    float* out = (float*)d_out;

    rnn_split_kernel<<<2 * BB, 256>>>(x, h0, W, U, b_ih, b_hh, out);
}